// round 12
// baseline (speedup 1.0000x reference)
#include <cuda_runtime.h>
#include <cuda_fp16.h>
#include <cstdint>

// ---------------- problem constants ----------------
#define NB      16384
#define F_IN    768
#define F_OUT   512
#define TILE_M  64           // batch rows per CTA (grid 256, 2 CTAs/SM)
#define NHALF   256          // N columns per pass
#define KC      64           // K elements per SMEM chunk
#define NKC     (F_IN / KC)  // 12 chunks
#define THREADS 128          // 4 warps

#define ROWB    144          // padded SMEM row stride (72 fp16) -> ldmatrix conflict-free
#define A_BUF_B (TILE_M * ROWB)   // 9216
#define B_BUF_B (NHALF  * ROWB)   // 36864

// smem layout (bytes, dynamic)
#define SM_B1    0                       // 512 f
#define SM_W2    2048                    // 1024 f
#define SM_PACC  6144                    // 64 f
#define SM_A     6656                    // 2 x 9216
#define SM_B     (6656 + 2*A_BUF_B)      // 2 x 36864
#define SMEM_TOTAL (SM_B + 2*B_BUF_B)    // 98816 bytes -> 2 CTAs/SM

// ---------------- fp16 weights scratch (device global: allowed) ----------------
__device__ __align__(16) __half g_w16[F_OUT * F_IN];

// ---------------- helpers ----------------
__device__ __forceinline__ uint32_t smem_u32(const void* p) {
    uint32_t a;
    asm("{ .reg .u64 t; cvta.to.shared.u64 t, %1; cvt.u32.u64 %0, t; }" : "=r"(a) : "l"(p));
    return a;
}

__device__ __forceinline__ void cp_async16(uint32_t dst, const void* src) {
    asm volatile("cp.async.cg.shared.global [%0], [%1], 16;\n" :: "r"(dst), "l"(src) : "memory");
}
__device__ __forceinline__ void cp_commit() {
    asm volatile("cp.async.commit_group;\n" ::: "memory");
}
template <int N>
__device__ __forceinline__ void cp_wait() {
    asm volatile("cp.async.wait_group %0;\n" :: "n"(N) : "memory");
}

__device__ __forceinline__ void ldsm_x4(uint32_t& r0, uint32_t& r1, uint32_t& r2, uint32_t& r3,
                                        uint32_t addr) {
    asm volatile("ldmatrix.sync.aligned.m8n8.x4.shared.b16 {%0,%1,%2,%3}, [%4];"
                 : "=r"(r0), "=r"(r1), "=r"(r2), "=r"(r3) : "r"(addr));
}

__device__ __forceinline__ void mma16816(float& c0, float& c1, float& c2, float& c3,
                                         uint32_t a0, uint32_t a1, uint32_t a2, uint32_t a3,
                                         uint32_t b0, uint32_t b1) {
    asm volatile(
        "mma.sync.aligned.m16n8k16.row.col.f32.f16.f16.f32 "
        "{%0,%1,%2,%3}, {%4,%5,%6,%7}, {%8,%9}, {%0,%1,%2,%3};"
        : "+f"(c0), "+f"(c1), "+f"(c2), "+f"(c3)
        : "r"(a0), "r"(a1), "r"(a2), "r"(a3), "r"(b0), "r"(b1));
}

// ---------------- prologue: W1 fp32 -> fp16 (0.75 MB, ~2us) ----------------
__global__ void cvt_w_kernel(const float* __restrict__ W1) {
    int i = blockIdx.x * blockDim.x + threadIdx.x;   // float4 index, total 98304
    float4 v = ((const float4*)W1)[i];
    __half2 h0 = __floats2half2_rn(v.x, v.y);
    __half2 h1 = __floats2half2_rn(v.z, v.w);
    uint2 pk;
    pk.x = *(uint32_t*)&h0;
    pk.y = *(uint32_t*)&h1;
    ((uint2*)g_w16)[i] = pk;
}

// ---------------- main fused kernel ----------------
__global__ void __launch_bounds__(THREADS, 2)
pnet_kernel(const float* __restrict__ stm, const float* __restrict__ nstm,
            const float* __restrict__ b1,  const float* __restrict__ W2,
            const float* __restrict__ b2,  float* __restrict__ out)
{
    extern __shared__ char smem[];
    const uint32_t sbase = smem_u32(smem);
    const int tid  = threadIdx.x;
    const int wid  = tid >> 5;
    const int lane = tid & 31;
    const int gid  = lane >> 2;   // row within 8 for MMA fragments
    const int tig  = lane & 3;    // col-pair within fragment

    const int warpN = wid * 64;   // 4 warps along N; every warp covers all 64 M rows

    float* b1s  = (float*)(smem + SM_B1);
    float* w2s  = (float*)(smem + SM_W2);
    float* pacc = (float*)(smem + SM_PACC);

    for (int i = tid; i < F_OUT; i += THREADS)     b1s[i] = b1[i];
    for (int i = tid; i < 2 * F_OUT; i += THREADS) w2s[i] = W2[i];
    if (tid < TILE_M) pacc[tid] = 0.0f;
    __syncthreads();

    const int rowbase = blockIdx.x * TILE_M;

    // ldmatrix lane address components
    const int lrow = lane & 15;
    const int lhi  = (lane >> 4) * 16;

    for (int p = 0; p < 2; p++) {
        const float* abase = (p ? nstm : stm) + (size_t)rowbase * F_IN;

        for (int nh = 0; nh < 2; nh++) {
            const __half* wbase = g_w16 + (size_t)nh * NHALF * F_IN;

            float acc[4][8][4];
            #pragma unroll
            for (int mt = 0; mt < 4; mt++)
                #pragma unroll
                for (int nt = 0; nt < 8; nt++)
                    #pragma unroll
                    for (int e = 0; e < 4; e++) acc[mt][nt][e] = 0.0f;

            // ---- prefetch chunk 0: A fp32 -> regs, B fp16 -> smem stage0 ----
            // A: 64 rows x 16 float4 = 1024 ops -> 8/thread (r = idx>>4, c = idx&15)
            // B: 256 rows x 8 x 16B  = 2048 ops -> 16/thread (r = idx>>3, c = idx&7)
            float4 regA[8];
            #pragma unroll
            for (int it = 0; it < 8; it++) {
                int idx = tid + it * THREADS;
                regA[it] = *(const float4*)(abase + (size_t)(idx >> 4) * F_IN + (idx & 15) * 4);
            }
            #pragma unroll
            for (int it = 0; it < 16; it++) {
                int idx = tid + it * THREADS;
                cp_async16(sbase + SM_B + (idx >> 3) * ROWB + (idx & 7) * 16,
                           wbase + (size_t)(idx >> 3) * F_IN + (idx & 7) * 8);
            }
            cp_commit();

            for (int kc = 0; kc < NKC; kc++) {
                const int buf = kc & 1;

                // convert + store A(kc) into this chunk's buffer
                #pragma unroll
                for (int it = 0; it < 8; it++) {
                    int idx = tid + it * THREADS;
                    __half2 h0 = __floats2half2_rn(regA[it].x, regA[it].y);
                    __half2 h1 = __floats2half2_rn(regA[it].z, regA[it].w);
                    uint2 pk;
                    pk.x = *(uint32_t*)&h0;
                    pk.y = *(uint32_t*)&h1;
                    *(uint2*)(smem + SM_A + buf * A_BUF_B + (idx >> 4) * ROWB + (idx & 15) * 8) = pk;
                }

                if (kc + 1 < NKC) {
                    // prefetch next chunk (hidden behind this chunk's MMAs)
                    const float* asrc = abase + (kc + 1) * KC;
                    #pragma unroll
                    for (int it = 0; it < 8; it++) {
                        int idx = tid + it * THREADS;
                        regA[it] = *(const float4*)(asrc + (size_t)(idx >> 4) * F_IN + (idx & 15) * 4);
                    }
                    const __half* wsrc = wbase + (size_t)(kc + 1) * KC;
                    const uint32_t dB = sbase + SM_B + ((kc + 1) & 1) * B_BUF_B;
                    #pragma unroll
                    for (int it = 0; it < 16; it++) {
                        int idx = tid + it * THREADS;
                        cp_async16(dB + (idx >> 3) * ROWB + (idx & 7) * 16,
                                   wsrc + (size_t)(idx >> 3) * F_IN + (idx & 7) * 8);
                    }
                    cp_commit();
                    cp_wait<1>();
                } else {
                    cp_wait<0>();
                }
                __syncthreads();   // A(kc) visible + B(kc) complete

                const uint32_t smA = sbase + SM_A + buf * A_BUF_B;
                const uint32_t smB = sbase + SM_B + buf * B_BUF_B;

                #pragma unroll
                for (int ks = 0; ks < 4; ks++) {       // 4 x k16 steps = K64
                    const int kb = ks * 32 + lhi;

                    uint32_t af[4][4];
                    uint32_t bf[4][4];
                    #pragma unroll
                    for (int mt = 0; mt < 4; mt++)
                        ldsm_x4(af[mt][0], af[mt][1], af[mt][2], af[mt][3],
                                smA + (mt * 16 + lrow) * ROWB + kb);
                    #pragma unroll
                    for (int nb = 0; nb < 4; nb++)
                        ldsm_x4(bf[nb][0], bf[nb][1], bf[nb][2], bf[nb][3],
                                smB + (warpN + nb * 16 + lrow) * ROWB + kb);

                    #pragma unroll
                    for (int nb = 0; nb < 4; nb++) {
                        #pragma unroll
                        for (int mt = 0; mt < 4; mt++) {
                            mma16816(acc[mt][2 * nb][0], acc[mt][2 * nb][1],
                                     acc[mt][2 * nb][2], acc[mt][2 * nb][3],
                                     af[mt][0], af[mt][1], af[mt][2], af[mt][3],
                                     bf[nb][0], bf[nb][2]);
                            mma16816(acc[mt][2 * nb + 1][0], acc[mt][2 * nb + 1][1],
                                     acc[mt][2 * nb + 1][2], acc[mt][2 * nb + 1][3],
                                     af[mt][0], af[mt][1], af[mt][2], af[mt][3],
                                     bf[nb][1], bf[nb][3]);
                        }
                    }
                }
                __syncthreads();   // all warps done reading buf before refill
            }

            // ---- epilogue for this (p, nh) pass ----
            const float* w2p = w2s + p * F_OUT;
            #pragma unroll
            for (int mt = 0; mt < 4; mt++) {
                #pragma unroll
                for (int j2 = 0; j2 < 2; j2++) {
                    const int row = mt * 16 + gid + j2 * 8;
                    float s = 0.0f;
                    #pragma unroll
                    for (int nt = 0; nt < 8; nt++) {
                        #pragma unroll
                        for (int j = 0; j < 2; j++) {
                            const int col = nh * NHALF + warpN + nt * 8 + tig * 2 + j;
                            float v = acc[mt][nt][j2 * 2 + j] + b1s[col];
                            v = __saturatef(v);
                            s = fmaf(v, w2p[col], s);
                        }
                    }
                    s += __shfl_xor_sync(0xFFFFFFFF, s, 1);
                    s += __shfl_xor_sync(0xFFFFFFFF, s, 2);
                    if (tig == 0) atomicAdd(&pacc[row], s);
                }
            }
        }
    }

    __syncthreads();
    if (tid < TILE_M) {
        float tot = pacc[tid] + b2[0];
        out[rowbase + tid] = 1.0f / (1.0f + __expf(-tot));
    }
}

// ---------------- launch ----------------
extern "C" void kernel_launch(void* const* d_in, const int* in_sizes, int n_in,
                              void* d_out, int out_size) {
    const float* stm  = (const float*)d_in[0];
    const float* nstm = (const float*)d_in[1];
    const float* W1   = (const float*)d_in[2];
    const float* b1   = (const float*)d_in[3];
    const float* W2   = (const float*)d_in[4];
    const float* b2   = (const float*)d_in[5];
    float* out = (float*)d_out;

    cvt_w_kernel<<<(F_OUT * F_IN / 4) / 256, 256>>>(W1);

    cudaFuncSetAttribute(pnet_kernel, cudaFuncAttributeMaxDynamicSharedMemorySize, SMEM_TOTAL);
    pnet_kernel<<<NB / TILE_M, THREADS, SMEM_TOTAL>>>(stm, nstm, b1, W2, b2, out);
}

// round 13
// speedup vs baseline: 1.0668x; 1.0668x over previous
#include <cuda_runtime.h>
#include <cuda_fp16.h>
#include <cstdint>

// ---------------- problem constants ----------------
#define NB      16384
#define F_IN    768
#define F_OUT   512
#define TILE_M  128          // batch rows per CTA (grid 128)
#define NHALF   256          // N columns per pass
#define NKSTEP  48           // k16 steps per pass (768/16)
#define THREADS 256          // 8 warps: 2 along M x 4 along N

#define ROWA    1552         // padded A row stride bytes (768*2 + 16): ldmatrix conflict-free

// smem layout (bytes, dynamic)
#define SM_B1    0                       // 512 f
#define SM_W2    2048                    // 1024 f
#define SM_PACC  6144                    // 128 f
#define SM_A     6656                    // 128 x 1552 = 198656
#define SMEM_TOTAL (SM_A + TILE_M * ROWA)    // 205312 bytes

// ---------------- fragment-formatted fp16 weights (device global: allowed) ----------------
// block index t = (((nh*4 + w)*48 + kstep)*4 + nb)*32 + lane ; each block = uint4 (8 fp16)
__device__ __align__(16) uint4 g_w16f[2 * 4 * NKSTEP * 4 * 32];

// ---------------- helpers ----------------
__device__ __forceinline__ uint32_t smem_u32(const void* p) {
    uint32_t a;
    asm("{ .reg .u64 t; cvta.to.shared.u64 t, %1; cvt.u32.u64 %0, t; }" : "=r"(a) : "l"(p));
    return a;
}

__device__ __forceinline__ void ldsm_x4(uint32_t& r0, uint32_t& r1, uint32_t& r2, uint32_t& r3,
                                        uint32_t addr) {
    asm volatile("ldmatrix.sync.aligned.m8n8.x4.shared.b16 {%0,%1,%2,%3}, [%4];"
                 : "=r"(r0), "=r"(r1), "=r"(r2), "=r"(r3) : "r"(addr));
}

__device__ __forceinline__ void mma16816(float& c0, float& c1, float& c2, float& c3,
                                         uint32_t a0, uint32_t a1, uint32_t a2, uint32_t a3,
                                         uint32_t b0, uint32_t b1) {
    asm volatile(
        "mma.sync.aligned.m16n8k16.row.col.f32.f16.f16.f32 "
        "{%0,%1,%2,%3}, {%4,%5,%6,%7}, {%8,%9}, {%0,%1,%2,%3};"
        : "+f"(c0), "+f"(c1), "+f"(c2), "+f"(c3)
        : "r"(a0), "r"(a1), "r"(a2), "r"(a3), "r"(b0), "r"(b1));
}

// ---------------- prologue: W1 fp32 -> fragment-linear fp16 ----------------
// One thread per 16B output block. For reg r of the block:
//   n = nh*256 + w*64 + nb*16 + (r&1)*8 + gid
//   k = kstep*16 + (r>>1)*8 + tig*2  (two halves: k, k+1)
// This reproduces exactly what ldmatrix.x4 (non-trans) over 16 n-rows x 32B used to
// deliver: MMA b-regs for n-low8 = (q.x, q.z), n-high8 = (q.y, q.w).
__global__ void fmt_w_kernel(const float* __restrict__ W1) {
    int t = blockIdx.x * blockDim.x + threadIdx.x;    // 0 .. 49151
    int lane  = t & 31;
    int nb    = (t >> 5) & 3;
    int kstep = (t >> 7) % NKSTEP;
    int rest  = (t >> 7) / NKSTEP;                    // nh*4 + w
    int w     = rest & 3;
    int nh    = rest >> 2;
    int gid = lane >> 2, tig = lane & 3;

    uint32_t q[4];
    #pragma unroll
    for (int r = 0; r < 4; r++) {
        int n = nh * 256 + w * 64 + nb * 16 + (r & 1) * 8 + gid;
        int k = kstep * 16 + (r >> 1) * 8 + tig * 2;
        __half2 h = __floats2half2_rn(W1[n * F_IN + k], W1[n * F_IN + k + 1]);
        q[r] = *(uint32_t*)&h;
    }
    uint4 v;
    v.x = q[0]; v.y = q[1]; v.z = q[2]; v.w = q[3];
    g_w16f[t] = v;
}

// ---------------- main fused kernel ----------------
__global__ void __launch_bounds__(THREADS, 1)
pnet_kernel(const float* __restrict__ stm, const float* __restrict__ nstm,
            const float* __restrict__ b1,  const float* __restrict__ W2,
            const float* __restrict__ b2,  float* __restrict__ out)
{
    extern __shared__ char smem[];
    const uint32_t sbase = smem_u32(smem);
    const int tid  = threadIdx.x;
    const int wid  = tid >> 5;
    const int lane = tid & 31;
    const int gid  = lane >> 2;
    const int tig  = lane & 3;

    const int warpM = (wid & 1) * 64;    // 2 warps along M
    const int wN    = wid >> 1;          // 4 warps along N
    const int warpN = wN * 64;

    float* b1s  = (float*)(smem + SM_B1);
    float* w2s  = (float*)(smem + SM_W2);
    float* pacc = (float*)(smem + SM_PACC);

    for (int i = tid; i < F_OUT; i += THREADS)     b1s[i] = b1[i];
    for (int i = tid; i < 2 * F_OUT; i += THREADS) w2s[i] = W2[i];
    if (tid < TILE_M) pacc[tid] = 0.0f;
    __syncthreads();

    const int rowbase = blockIdx.x * TILE_M;

    // ldmatrix lane address components (A side)
    const int lrow = lane & 15;
    const int lhi  = (lane >> 4) * 16;

    for (int p = 0; p < 2; p++) {
        // ---- A phase: convert whole 128x768 fp32 tile -> fp16 smem (once per p) ----
        {
            const float4* a4 = (const float4*)((p ? nstm : stm) + (size_t)rowbase * F_IN);
            #pragma unroll 4
            for (int it = 0; it < 96; it++) {          // 24576 float4 / 256 threads
                int idx = it * THREADS + tid;
                float4 v = a4[idx];
                int r = idx / 192;                      // 192 float4 per row
                int c = idx - r * 192;
                __half2 h0 = __floats2half2_rn(v.x, v.y);
                __half2 h1 = __floats2half2_rn(v.z, v.w);
                uint2 pk;
                pk.x = *(uint32_t*)&h0;
                pk.y = *(uint32_t*)&h1;
                *(uint2*)(smem + SM_A + r * ROWA + c * 8) = pk;
            }
        }
        __syncthreads();   // A resident for the whole perspective

        for (int nh = 0; nh < 2; nh++) {
            const uint4* wf = g_w16f + (size_t)(nh * 4 + wN) * NKSTEP * 128;

            float acc[4][8][4];
            #pragma unroll
            for (int mt = 0; mt < 4; mt++)
                #pragma unroll
                for (int nt = 0; nt < 8; nt++)
                    #pragma unroll
                    for (int e = 0; e < 4; e++) acc[mt][nt][e] = 0.0f;

            // preload B fragments for kstep 0
            uint4 bfrag[2][4];
            #pragma unroll
            for (int nb = 0; nb < 4; nb++)
                bfrag[0][nb] = wf[nb * 32 + lane];

            // ---- barrier-free mainloop: 48 k16 steps ----
            #pragma unroll 2
            for (int kstep = 0; kstep < NKSTEP; kstep++) {
                const int cur = kstep & 1;

                // prefetch next kstep's B fragments (L2/L1-resident, regs only)
                if (kstep + 1 < NKSTEP) {
                    const uint4* wn = wf + (size_t)(kstep + 1) * 128;
                    #pragma unroll
                    for (int nb = 0; nb < 4; nb++)
                        bfrag[cur ^ 1][nb] = wn[nb * 32 + lane];
                }

                const uint32_t kb = kstep * 32 + lhi;
                uint32_t af[4][4];
                #pragma unroll
                for (int mt = 0; mt < 4; mt++)
                    ldsm_x4(af[mt][0], af[mt][1], af[mt][2], af[mt][3],
                            sbase + SM_A + (warpM + mt * 16 + lrow) * ROWA + kb);

                #pragma unroll
                for (int nb = 0; nb < 4; nb++) {
                    #pragma unroll
                    for (int mt = 0; mt < 4; mt++) {
                        mma16816(acc[mt][2 * nb][0], acc[mt][2 * nb][1],
                                 acc[mt][2 * nb][2], acc[mt][2 * nb][3],
                                 af[mt][0], af[mt][1], af[mt][2], af[mt][3],
                                 bfrag[cur][nb].x, bfrag[cur][nb].z);
                        mma16816(acc[mt][2 * nb + 1][0], acc[mt][2 * nb + 1][1],
                                 acc[mt][2 * nb + 1][2], acc[mt][2 * nb + 1][3],
                                 af[mt][0], af[mt][1], af[mt][2], af[mt][3],
                                 bfrag[cur][nb].y, bfrag[cur][nb].w);
                    }
                }
            }

            // ---- epilogue for this (p, nh) pass ----
            const float* w2p = w2s + p * F_OUT;
            #pragma unroll
            for (int mt = 0; mt < 4; mt++) {
                #pragma unroll
                for (int j2 = 0; j2 < 2; j2++) {
                    const int row = warpM + mt * 16 + gid + j2 * 8;
                    float s = 0.0f;
                    #pragma unroll
                    for (int nt = 0; nt < 8; nt++) {
                        #pragma unroll
                        for (int j = 0; j < 2; j++) {
                            const int col = nh * NHALF + warpN + nt * 8 + tig * 2 + j;
                            float v = acc[mt][nt][j2 * 2 + j] + b1s[col];
                            v = __saturatef(v);
                            s = fmaf(v, w2p[col], s);
                        }
                    }
                    s += __shfl_xor_sync(0xFFFFFFFF, s, 1);
                    s += __shfl_xor_sync(0xFFFFFFFF, s, 2);
                    if (tig == 0) atomicAdd(&pacc[row], s);
                }
            }
        }
        __syncthreads();   // all A reads done before next p overwrites smem A
    }

    if (tid < TILE_M) {
        float tot = pacc[tid] + b2[0];
        out[rowbase + tid] = 1.0f / (1.0f + __expf(-tot));
    }
}

// ---------------- launch ----------------
extern "C" void kernel_launch(void* const* d_in, const int* in_sizes, int n_in,
                              void* d_out, int out_size) {
    const float* stm  = (const float*)d_in[0];
    const float* nstm = (const float*)d_in[1];
    const float* W1   = (const float*)d_in[2];
    const float* b1   = (const float*)d_in[3];
    const float* W2   = (const float*)d_in[4];
    const float* b2   = (const float*)d_in[5];
    float* out = (float*)d_out;

    fmt_w_kernel<<<(2 * 4 * NKSTEP * 4 * 32) / 256, 256>>>(W1);

    cudaFuncSetAttribute(pnet_kernel, cudaFuncAttributeMaxDynamicSharedMemorySize, SMEM_TOTAL);
    pnet_kernel<<<NB / TILE_M, THREADS, SMEM_TOTAL>>>(stm, nstm, b1, W2, b2, out);
}

// round 15
// speedup vs baseline: 1.2305x; 1.1534x over previous
#include <cuda_runtime.h>
#include <cuda_fp16.h>
#include <cstdint>

// ---------------- problem constants ----------------
#define NB      16384
#define F_IN    768
#define F_OUT   512
#define TILE_M  128          // batch rows per CTA (grid 128)
#define NHALF   256          // N columns per pass
#define NKSTEP  48           // k16 steps per pass (768/16)
#define THREADS 512          // 16 warps: 4 along M x 4 along N

#define ROWA    1552         // padded A row stride bytes (768*2 + 16): ldmatrix conflict-free

// smem layout (bytes, dynamic)
#define SM_B1    0                       // 512 f
#define SM_W2    2048                    // 1024 f
#define SM_PACC  6144                    // 128 f
#define SM_A     6656                    // 128 x 1552 = 198656
#define SMEM_TOTAL (SM_A + TILE_M * ROWA)    // 205312 bytes

// ---------------- fragment-formatted fp16 weights (device global: allowed) ----------------
// block index t = (((nh*4 + w)*48 + kstep)*4 + nb)*32 + lane ; each block = uint4 (8 fp16)
__device__ __align__(16) uint4 g_w16f[2 * 4 * NKSTEP * 4 * 32];

// ---------------- helpers ----------------
__device__ __forceinline__ uint32_t smem_u32(const void* p) {
    uint32_t a;
    asm("{ .reg .u64 t; cvta.to.shared.u64 t, %1; cvt.u32.u64 %0, t; }" : "=r"(a) : "l"(p));
    return a;
}

__device__ __forceinline__ void ldsm_x4(uint32_t& r0, uint32_t& r1, uint32_t& r2, uint32_t& r3,
                                        uint32_t addr) {
    asm volatile("ldmatrix.sync.aligned.m8n8.x4.shared.b16 {%0,%1,%2,%3}, [%4];"
                 : "=r"(r0), "=r"(r1), "=r"(r2), "=r"(r3) : "r"(addr));
}

__device__ __forceinline__ void mma16816(float& c0, float& c1, float& c2, float& c3,
                                         uint32_t a0, uint32_t a1, uint32_t a2, uint32_t a3,
                                         uint32_t b0, uint32_t b1) {
    asm volatile(
        "mma.sync.aligned.m16n8k16.row.col.f32.f16.f16.f32 "
        "{%0,%1,%2,%3}, {%4,%5,%6,%7}, {%8,%9}, {%0,%1,%2,%3};"
        : "+f"(c0), "+f"(c1), "+f"(c2), "+f"(c3)
        : "r"(a0), "r"(a1), "r"(a2), "r"(a3), "r"(b0), "r"(b1));
}

// ---------------- prologue: W1 fp32 -> fragment-linear fp16 ----------------
// One thread per 16B output block. For reg r of the block:
//   n = nh*256 + w*64 + nb*16 + (r&1)*8 + gid
//   k = kstep*16 + (r>>1)*8 + tig*2  (two halves: k, k+1)
// Reproduces exactly what ldmatrix.x4 (non-trans) over 16 n-rows x 32B delivers:
// MMA b-regs for n-low8 = (q.x, q.z), n-high8 = (q.y, q.w).
__global__ void fmt_w_kernel(const float* __restrict__ W1) {
    int t = blockIdx.x * blockDim.x + threadIdx.x;    // 0 .. 49151
    int lane  = t & 31;
    int nb    = (t >> 5) & 3;
    int kstep = (t >> 7) % NKSTEP;
    int rest  = (t >> 7) / NKSTEP;                    // nh*4 + w
    int w     = rest & 3;
    int nh    = rest >> 2;
    int gid = lane >> 2, tig = lane & 3;

    uint32_t q[4];
    #pragma unroll
    for (int r = 0; r < 4; r++) {
        int n = nh * 256 + w * 64 + nb * 16 + (r & 1) * 8 + gid;
        int k = kstep * 16 + (r >> 1) * 8 + tig * 2;
        __half2 h = __floats2half2_rn(W1[n * F_IN + k], W1[n * F_IN + k + 1]);
        q[r] = *(uint32_t*)&h;
    }
    uint4 v;
    v.x = q[0]; v.y = q[1]; v.z = q[2]; v.w = q[3];
    g_w16f[t] = v;
}

// ---------------- main fused kernel ----------------
__global__ void __launch_bounds__(THREADS, 1)
pnet_kernel(const float* __restrict__ stm, const float* __restrict__ nstm,
            const float* __restrict__ b1,  const float* __restrict__ W2,
            const float* __restrict__ b2,  float* __restrict__ out)
{
    extern __shared__ char smem[];
    const uint32_t sbase = smem_u32(smem);
    const int tid  = threadIdx.x;
    const int wid  = tid >> 5;
    const int lane = tid & 31;
    const int gid  = lane >> 2;
    const int tig  = lane & 3;

    const int warpM = (wid & 3) * 32;    // 4 warps along M (32 rows each)
    const int wN    = wid >> 2;          // 4 warps along N
    const int warpN = wN * 64;

    float* b1s  = (float*)(smem + SM_B1);
    float* w2s  = (float*)(smem + SM_W2);
    float* pacc = (float*)(smem + SM_PACC);

    for (int i = tid; i < F_OUT; i += THREADS)     b1s[i] = b1[i];
    for (int i = tid; i < 2 * F_OUT; i += THREADS) w2s[i] = W2[i];
    if (tid < TILE_M) pacc[tid] = 0.0f;
    __syncthreads();

    const int rowbase = blockIdx.x * TILE_M;

    // ldmatrix lane address components (A side)
    const int lrow = lane & 15;
    const int lhi  = (lane >> 4) * 16;

    for (int p = 0; p < 2; p++) {
        // ---- A phase: convert whole 128x768 fp32 tile -> fp16 smem (once per p) ----
        {
            const float4* a4 = (const float4*)((p ? nstm : stm) + (size_t)rowbase * F_IN);
            #pragma unroll 4
            for (int it = 0; it < 48; it++) {          // 24576 float4 / 512 threads
                int idx = it * THREADS + tid;
                float4 v = a4[idx];
                int r = idx / 192;                      // 192 float4 per row
                int c = idx - r * 192;
                __half2 h0 = __floats2half2_rn(v.x, v.y);
                __half2 h1 = __floats2half2_rn(v.z, v.w);
                uint2 pk;
                pk.x = *(uint32_t*)&h0;
                pk.y = *(uint32_t*)&h1;
                *(uint2*)(smem + SM_A + r * ROWA + c * 8) = pk;
            }
        }
        __syncthreads();   // A resident for the whole perspective

        for (int nh = 0; nh < 2; nh++) {
            const uint4* wf = g_w16f + (size_t)(nh * 4 + wN) * NKSTEP * 128;

            float acc[2][8][4];
            #pragma unroll
            for (int mt = 0; mt < 2; mt++)
                #pragma unroll
                for (int nt = 0; nt < 8; nt++)
                    #pragma unroll
                    for (int e = 0; e < 4; e++) acc[mt][nt][e] = 0.0f;

            // preload B fragments for kstep 0
            uint4 bfrag[2][4];
            #pragma unroll
            for (int nb = 0; nb < 4; nb++)
                bfrag[0][nb] = wf[nb * 32 + lane];

            // ---- barrier-free mainloop: 48 k16 steps ----
            #pragma unroll 2
            for (int kstep = 0; kstep < NKSTEP; kstep++) {
                const int cur = kstep & 1;

                // prefetch next kstep's B fragments (regs only; 4 warps share slice -> L1 hits)
                if (kstep + 1 < NKSTEP) {
                    const uint4* wn = wf + (size_t)(kstep + 1) * 128;
                    #pragma unroll
                    for (int nb = 0; nb < 4; nb++)
                        bfrag[cur ^ 1][nb] = wn[nb * 32 + lane];
                }

                const uint32_t kb = kstep * 32 + lhi;
                uint32_t af[2][4];
                #pragma unroll
                for (int mt = 0; mt < 2; mt++)
                    ldsm_x4(af[mt][0], af[mt][1], af[mt][2], af[mt][3],
                            sbase + SM_A + (warpM + mt * 16 + lrow) * ROWA + kb);

                #pragma unroll
                for (int nb = 0; nb < 4; nb++) {
                    #pragma unroll
                    for (int mt = 0; mt < 2; mt++) {
                        mma16816(acc[mt][2 * nb][0], acc[mt][2 * nb][1],
                                 acc[mt][2 * nb][2], acc[mt][2 * nb][3],
                                 af[mt][0], af[mt][1], af[mt][2], af[mt][3],
                                 bfrag[cur][nb].x, bfrag[cur][nb].z);
                        mma16816(acc[mt][2 * nb + 1][0], acc[mt][2 * nb + 1][1],
                                 acc[mt][2 * nb + 1][2], acc[mt][2 * nb + 1][3],
                                 af[mt][0], af[mt][1], af[mt][2], af[mt][3],
                                 bfrag[cur][nb].y, bfrag[cur][nb].w);
                    }
                }
            }

            // ---- epilogue for this (p, nh) pass ----
            const float* w2p = w2s + p * F_OUT;
            #pragma unroll
            for (int mt = 0; mt < 2; mt++) {
                #pragma unroll
                for (int j2 = 0; j2 < 2; j2++) {
                    const int row = warpM + mt * 16 + gid + j2 * 8;
                    float s = 0.0f;
                    #pragma unroll
                    for (int nt = 0; nt < 8; nt++) {
                        #pragma unroll
                        for (int j = 0; j < 2; j++) {
                            const int col = nh * NHALF + warpN + nt * 8 + tig * 2 + j;
                            float v = acc[mt][nt][j2 * 2 + j] + b1s[col];
                            v = __saturatef(v);
                            s = fmaf(v, w2p[col], s);
                        }
                    }
                    s += __shfl_xor_sync(0xFFFFFFFF, s, 1);
                    s += __shfl_xor_sync(0xFFFFFFFF, s, 2);
                    if (tig == 0) atomicAdd(&pacc[row], s);
                }
            }
        }
        __syncthreads();   // all A reads done before next p overwrites smem A
    }

    if (tid < TILE_M) {
        float tot = pacc[tid] + b2[0];
        out[rowbase + tid] = 1.0f / (1.0f + __expf(-tot));
    }
}

// ---------------- launch ----------------
extern "C" void kernel_launch(void* const* d_in, const int* in_sizes, int n_in,
                              void* d_out, int out_size) {
    const float* stm  = (const float*)d_in[0];
    const float* nstm = (const float*)d_in[1];
    const float* W1   = (const float*)d_in[2];
    const float* b1   = (const float*)d_in[3];
    const float* W2   = (const float*)d_in[4];
    const float* b2   = (const float*)d_in[5];
    float* out = (float*)d_out;

    fmt_w_kernel<<<(2 * 4 * NKSTEP * 4 * 32) / 256, 256>>>(W1);

    cudaFuncSetAttribute(pnet_kernel, cudaFuncAttributeMaxDynamicSharedMemorySize, SMEM_TOTAL);
    pnet_kernel<<<NB / TILE_M, THREADS, SMEM_TOTAL>>>(stm, nstm, b1, W2, b2, out);
}